// round 8
// baseline (speedup 1.0000x reference)
#include <cuda_runtime.h>
#include <math.h>

#define BATCH 16
#define HID   512
#define NN    2048

#define KBLK   128              // threads per block in gemv = k-values per block
#define KCH    (HID / KBLK)     // 4 k-chunks
#define HCH    32               // h-chunks
#define HPER   (HID / HCH)      // 16 h per chunk

#define RS_BLOCKS_PER_BATCH (NN / 8)   // 256 rowsum blocks per batch (8 rows/block)

// Scratch (allocation-free rule: __device__ globals)
__device__ float g_d[BATCH * NN];            // d[b,m] = rsqrt(rowsum)
__device__ float g_w[BATCH * NN];            // w[b,m]
__device__ float g_y[BATCH * HID];           // y[b,h]
__device__ float g_part[HCH * BATCH * HID];  // partial GEMV sums
__device__ int   g_ctr_b[BATCH];             // rowsum completion counters (start 0)
__device__ int   g_ctr_kc[KCH];              // gemv completion counters (start 0)

// ---------------------------------------------------------------------------
// Kernel 1: per-row rsqrt(rowsum) of clip(adj,0)+I.  One warp per row.
// The LAST block to finish in each batch also computes w[b,:] inline
// (deterministic: fixed order, counter returns to 0 every run).
// ---------------------------------------------------------------------------
__global__ void rowsum_kernel(const float* __restrict__ adj) {
    __shared__ int s_last;
    int warp = (blockIdx.x * blockDim.x + threadIdx.x) >> 5;
    int lane = threadIdx.x & 31;
    int b = (int)(blockIdx.x / RS_BLOCKS_PER_BATCH);   // 8 rows/block, same batch

    const float4* row = (const float4*)(adj + (size_t)warp * NN);
    float s = 0.f;
#pragma unroll
    for (int i = 0; i < NN / (4 * 32); ++i) {
        float4 v = row[lane + i * 32];
        s += fmaxf(v.x, 0.f) + fmaxf(v.y, 0.f) + fmaxf(v.z, 0.f) + fmaxf(v.w, 0.f);
    }
#pragma unroll
    for (int o = 16; o; o >>= 1) s += __shfl_xor_sync(0xffffffffu, s, o);
    if (lane == 0) g_d[warp] = rsqrtf(s + 1.0f);

    // last-block-per-batch computes w[b,:]
    __syncthreads();
    if (threadIdx.x == 0) {
        __threadfence();                       // release all this block's g_d stores
        int old = atomicAdd(&g_ctr_b[b], 1);
        s_last = (old == RS_BLOCKS_PER_BATCH - 1);
    }
    __syncthreads();
    if (s_last) {
        __threadfence();                       // acquire other blocks' g_d stores
        float d0 = g_d[b * NN];
        const float* arow = adj + (size_t)b * NN * NN;   // adj[b,0,:]
        for (int m = threadIdx.x; m < NN; m += blockDim.x) {
            float a = fmaxf(arow[m], 0.f) + (m == 0 ? 1.0f : 0.0f);
            g_w[b * NN + m] = d0 * a * g_d[b * NN + m];
        }
        if (threadIdx.x == 0) g_ctr_b[b] = 0;  // reset for next replay
    }
}

// ---------------------------------------------------------------------------
// Kernel 2: y[b,h] = dot(w[b,:], feat[b,h,:]). One warp per (b,h).
// ---------------------------------------------------------------------------
__global__ void reduce_kernel(const float* __restrict__ feat) {
    int warp = (blockIdx.x * blockDim.x + threadIdx.x) >> 5;
    int lane = threadIdx.x & 31;
    if (warp >= BATCH * HID) return;
    int b = warp / HID;

    const float4* f  = (const float4*)(feat + (size_t)warp * NN);
    const float4* wp = (const float4*)(g_w + b * NN);
    float s = 0.f;
#pragma unroll
    for (int i = 0; i < NN / (4 * 32); ++i) {
        float4 fv = f[lane + i * 32];
        float4 wv = wp[lane + i * 32];
        s += fv.x * wv.x + fv.y * wv.y + fv.z * wv.z + fv.w * wv.w;
    }
#pragma unroll
    for (int o = 16; o; o >>= 1) s += __shfl_xor_sync(0xffffffffu, s, o);
    if (lane == 0) g_y[warp] = s;
}

// ---------------------------------------------------------------------------
// Kernel 3: batch-shared GEMV partials + fused finish.
// grid=(KCH, HCH)=128 blocks, 128 thr. Thread t holds all 16 batch
// accumulators; each W[h,k] load feeds 16 FMAs (W read exactly once).
// The LAST hc-block per kc sums the 32 partials + bias, applies tanh,
// writes out for its 128 k-columns (L2-hot reads). Deterministic order.
// ---------------------------------------------------------------------------
__global__ void gemv_kernel(const float* __restrict__ Wmat,
                            const float* __restrict__ bias,
                            float* __restrict__ out) {
    __shared__ float ys[BATCH * HPER];  // 256 floats
    __shared__ int s_last;
    int kc = blockIdx.x;
    int hc = blockIdx.y;
    int t  = threadIdx.x;
    int k  = kc * KBLK + t;

    for (int i = t; i < BATCH * HPER; i += KBLK) {
        int b = i / HPER, h = i - b * HPER;
        ys[i] = g_y[b * HID + hc * HPER + h];
    }
    __syncthreads();

    float acc[BATCH];
#pragma unroll
    for (int b = 0; b < BATCH; ++b) acc[b] = 0.f;

#pragma unroll
    for (int h = 0; h < HPER; ++h) {
        float w = Wmat[(size_t)(hc * HPER + h) * HID + k];  // coalesced
#pragma unroll
        for (int b = 0; b < BATCH; ++b)
            acc[b] = fmaf(ys[b * HPER + h], w, acc[b]);
    }

#pragma unroll
    for (int b = 0; b < BATCH; ++b)
        g_part[(size_t)(hc * BATCH + b) * HID + k] = acc[b];  // coalesced

    // last-block-per-kc does the finish
    __syncthreads();
    if (t == 0) {
        __threadfence();                    // release this block's partials
        int old = atomicAdd(&g_ctr_kc[kc], 1);
        s_last = (old == HCH - 1);
    }
    __syncthreads();
    if (s_last) {
        __threadfence();                    // acquire all partials
#pragma unroll 4
        for (int b = 0; b < BATCH; ++b) {
            float a = bias[b * HID + k];
#pragma unroll
            for (int c = 0; c < HCH; ++c)
                a += g_part[(size_t)(c * BATCH + b) * HID + k];
            out[b * HID + k] = tanhf(a);
        }
        if (t == 0) g_ctr_kc[kc] = 0;       // reset for next replay
    }
}

// ---------------------------------------------------------------------------
extern "C" void kernel_launch(void* const* d_in, const int* in_sizes, int n_in,
                              void* d_out, int out_size) {
    const float* feat = (const float*)d_in[0];  // [B, H, N]
    const float* adj  = (const float*)d_in[1];  // [B, N, N]
    const float* Wm   = (const float*)d_in[2];  // [H, H]
    const float* bias = (const float*)d_in[3];  // [B, H]
    float* out = (float*)d_out;                 // [B, H]

    rowsum_kernel<<<(BATCH * NN) / 8, 256>>>(adj);
    reduce_kernel<<<(BATCH * HID) / 8, 256>>>(feat);
    dim3 g3(KCH, HCH);
    gemv_kernel<<<g3, KBLK>>>(Wm, bias, out);
}

// round 13
// speedup vs baseline: 1.0785x; 1.0785x over previous
#include <cuda_runtime.h>
#include <math.h>

#define BATCH 16
#define HID   512
#define NN    2048

#define KBLK   128              // threads per block in gemv = k-values per block
#define KCH    (HID / KBLK)     // 4 k-chunks
#define HCH    32               // h-chunks
#define HPER   (HID / HCH)      // 16 h per chunk

// Scratch (allocation-free rule: __device__ globals)
__device__ float g_d[BATCH * NN];            // d[b,m] = rsqrt(rowsum)
__device__ float g_w[BATCH * NN];            // w[b,m]
__device__ float g_y[BATCH * HID];           // y[b,h]
__device__ float g_part[HCH * BATCH * HID];  // partial GEMV sums
__device__ int   g_ctr_kc[KCH];              // gemv completion counters (start 0)

// ---------------------------------------------------------------------------
// Kernel 1: per-row rsqrt(rowsum) of clip(adj,0)+I. One warp per row.
// Streaming loads (__ldcs): adj has zero reuse — don't pollute L2.
// ---------------------------------------------------------------------------
__global__ void rowsum_kernel(const float* __restrict__ adj) {
    int warp = (blockIdx.x * blockDim.x + threadIdx.x) >> 5;
    int lane = threadIdx.x & 31;
    if (warp >= BATCH * NN) return;

    const float4* row = (const float4*)(adj + (size_t)warp * NN);
    float s = 0.f;
#pragma unroll
    for (int i = 0; i < NN / (4 * 32); ++i) {
        float4 v = __ldcs(row + lane + i * 32);
        s += fmaxf(v.x, 0.f) + fmaxf(v.y, 0.f) + fmaxf(v.z, 0.f) + fmaxf(v.w, 0.f);
    }
#pragma unroll
    for (int o = 16; o; o >>= 1) s += __shfl_xor_sync(0xffffffffu, s, o);
    if (lane == 0) g_d[warp] = rsqrtf(s + 1.0f);
}

// ---------------------------------------------------------------------------
// Kernel 2 (tiny): w[b,m] = d[b,0] * (clip(adj[b,0,m],0) + [m==0]) * d[b,m]
// ---------------------------------------------------------------------------
__global__ void weight_kernel(const float* __restrict__ adj) {
    int idx = blockIdx.x * blockDim.x + threadIdx.x;
    if (idx >= BATCH * NN) return;
    int b = idx / NN;
    int m = idx - b * NN;
    float a = fmaxf(adj[(size_t)b * NN * NN + m], 0.f) + (m == 0 ? 1.0f : 0.0f);
    g_w[idx] = g_d[b * NN] * a * g_d[idx];
}

// ---------------------------------------------------------------------------
// Kernel 3: y[b,h] = dot(w[b,:], feat[b,h,:]). One warp per (b,h).
// feat streamed (__ldcs); w rows stay cached (default policy).
// ---------------------------------------------------------------------------
__global__ void reduce_kernel(const float* __restrict__ feat) {
    int warp = (blockIdx.x * blockDim.x + threadIdx.x) >> 5;
    int lane = threadIdx.x & 31;
    if (warp >= BATCH * HID) return;
    int b = warp / HID;

    const float4* f  = (const float4*)(feat + (size_t)warp * NN);
    const float4* wp = (const float4*)(g_w + b * NN);
    float s = 0.f;
#pragma unroll
    for (int i = 0; i < NN / (4 * 32); ++i) {
        float4 fv = __ldcs(f + lane + i * 32);
        float4 wv = wp[lane + i * 32];
        s += fv.x * wv.x + fv.y * wv.y + fv.z * wv.z + fv.w * wv.w;
    }
#pragma unroll
    for (int o = 16; o; o >>= 1) s += __shfl_xor_sync(0xffffffffu, s, o);
    if (lane == 0) g_y[warp] = s;
}

// ---------------------------------------------------------------------------
// Kernel 4: batch-shared GEMV partials + fused finish (low-risk: 128 blocks).
// Thread t holds all 16 batch accumulators; each W[h,k] load feeds 16 FMAs.
// Last hc-block per kc sums 32 partials + bias, tanh, writes out (L2-hot).
// Deterministic: fixed summation order, counters net to 0 each replay.
// ---------------------------------------------------------------------------
__global__ void gemv_kernel(const float* __restrict__ Wmat,
                            const float* __restrict__ bias,
                            float* __restrict__ out) {
    __shared__ float ys[BATCH * HPER];  // 256 floats
    __shared__ int s_last;
    int kc = blockIdx.x;
    int hc = blockIdx.y;
    int t  = threadIdx.x;
    int k  = kc * KBLK + t;

    for (int i = t; i < BATCH * HPER; i += KBLK) {
        int b = i / HPER, h = i - b * HPER;
        ys[i] = g_y[b * HID + hc * HPER + h];
    }
    __syncthreads();

    float acc[BATCH];
#pragma unroll
    for (int b = 0; b < BATCH; ++b) acc[b] = 0.f;

#pragma unroll
    for (int h = 0; h < HPER; ++h) {
        float w = Wmat[(size_t)(hc * HPER + h) * HID + k];  // coalesced
#pragma unroll
        for (int b = 0; b < BATCH; ++b)
            acc[b] = fmaf(ys[b * HPER + h], w, acc[b]);
    }

#pragma unroll
    for (int b = 0; b < BATCH; ++b)
        g_part[(size_t)(hc * BATCH + b) * HID + k] = acc[b];  // coalesced

    __syncthreads();
    if (t == 0) {
        __threadfence();                    // release this block's partials
        int old = atomicAdd(&g_ctr_kc[kc], 1);
        s_last = (old == HCH - 1);
    }
    __syncthreads();
    if (s_last) {
        __threadfence();                    // acquire all partials
#pragma unroll 4
        for (int b = 0; b < BATCH; ++b) {
            float a = bias[b * HID + k];
#pragma unroll
            for (int c = 0; c < HCH; ++c)
                a += g_part[(size_t)(c * BATCH + b) * HID + k];
            out[b * HID + k] = tanhf(a);
        }
        if (t == 0) g_ctr_kc[kc] = 0;       // reset for next replay
    }
}

// ---------------------------------------------------------------------------
extern "C" void kernel_launch(void* const* d_in, const int* in_sizes, int n_in,
                              void* d_out, int out_size) {
    const float* feat = (const float*)d_in[0];  // [B, H, N]
    const float* adj  = (const float*)d_in[1];  // [B, N, N]
    const float* Wm   = (const float*)d_in[2];  // [H, H]
    const float* bias = (const float*)d_in[3];  // [B, H]
    float* out = (float*)d_out;                 // [B, H]

    rowsum_kernel<<<(BATCH * NN) / 8, 256>>>(adj);
    weight_kernel<<<(BATCH * NN + 255) / 256, 256>>>(adj);
    reduce_kernel<<<(BATCH * HID) / 8, 256>>>(feat);
    dim3 g4(KCH, HCH);
    gemv_kernel<<<g4, KBLK>>>(Wm, bias, out);
}